// round 6
// baseline (speedup 1.0000x reference)
#include <cuda_runtime.h>
#include <cstddef>

#define T_STEPS 8192
#define NRES    2048
#define DIN     64
#define DOUT    64
#define GBLK    128          // CTAs; 16 rows each (RF-forced: W lives in registers)
#define TPB     256
#define LEAK    0.3f
#define NOISE_L 0.01f
#define TILE_T  128

// ---------------- scratch (device globals: allocation-free) ----------------
__device__ float g_drive [T_STEPS * NRES];              // 64 MB
__device__ float g_states[T_STEPS * NRES];              // 64 MB
__device__ unsigned long long g_ex[2][NRES];            // (tag<<32)|valbits, dbl-buffered

// ---------------- kernel 0: reset exchange buffers (determinism) ------------
__global__ void init_kernel() {
    int i = blockIdx.x * blockDim.x + threadIdx.x;
    if (i < NRES) {
        g_ex[0][i] = 0ULL;                   // tag 0 == step 0, value 0.0f
        g_ex[1][i] = 0xFFFFFFFF00000000ULL;  // never-matching tag
    }
}

// ---------------- kernel 1: drive = u @ W_in^T + 0.01*noise -----------------
__global__ void drive_kernel(const float* __restrict__ u,
                             const float* __restrict__ noise,
                             const float* __restrict__ W_in) {
    __shared__ float4 u_sh[TILE_T * (DIN / 4)];
    const int n  = blockIdx.x * 256 + threadIdx.x;
    const int t0 = blockIdx.y * TILE_T;

    float4 w[DIN / 4];
    const float4* Wv = reinterpret_cast<const float4*>(W_in);
    #pragma unroll
    for (int j = 0; j < DIN / 4; j++) w[j] = Wv[(size_t)n * (DIN / 4) + j];

    const float4* uv = reinterpret_cast<const float4*>(u + (size_t)t0 * DIN);
    for (int i = threadIdx.x; i < TILE_T * (DIN / 4); i += 256) u_sh[i] = uv[i];
    __syncthreads();

    for (int t = 0; t < TILE_T; t++) {
        float acc = 0.f;
        #pragma unroll
        for (int j = 0; j < DIN / 4; j++) {
            float4 uu = u_sh[t * (DIN / 4) + j];
            acc += w[j].x * uu.x + w[j].y * uu.y + w[j].z * uu.z + w[j].w * uu.w;
        }
        size_t idx = (size_t)(t0 + t) * NRES + n;
        g_drive[idx] = acc + NOISE_L * noise[idx];
    }
}

// ---------------- kernel 2: persistent reservoir ----------------------------
// 128 CTAs x 256 thr; CTA owns 16 rows; warp owns 2 rows; lane owns 64 cols.
// Publish: in-band tagged 8B words (no fences/atomics).
// Detect:  threads 0..127 each own ONE producer CTA's 128B line; warps 4-7
//          park at the barrier (no grid-wide spin storm).
__global__ void __launch_bounds__(TPB, 1) reservoir_kernel(const float* __restrict__ W) {
    __shared__ float s_sh[2][NRES];           // double-buffered staged state

    const int tid  = threadIdx.x;
    const int cta  = blockIdx.x;
    const int warp = tid >> 5;
    const int lane = tid & 31;
    const int r0   = cta * 16 + warp * 2;

    // One-time: load W slice, pack column pairs into 64-bit (f32x2) registers
    const float4* Wv = reinterpret_cast<const float4*>(W);
    unsigned long long w0[32], w1[32];
    #pragma unroll
    for (int j = 0; j < 16; j++) {
        float4 a = Wv[(size_t)r0 * (NRES / 4) + lane + 32 * j];
        float4 b = Wv[(size_t)(r0 + 1) * (NRES / 4) + lane + 32 * j];
        w0[2*j]   = ((unsigned long long)__float_as_uint(a.y) << 32) | __float_as_uint(a.x);
        w0[2*j+1] = ((unsigned long long)__float_as_uint(a.w) << 32) | __float_as_uint(a.z);
        w1[2*j]   = ((unsigned long long)__float_as_uint(b.y) << 32) | __float_as_uint(b.x);
        w1[2*j+1] = ((unsigned long long)__float_as_uint(b.w) << 32) | __float_as_uint(b.z);
    }

    const bool pub   = (lane & 15) == 0;      // lanes 0 and 16 publish
    const int  myrow = r0 + (lane >> 4);      // lane0 -> r0, lane16 -> r0+1
    float sp   = 0.f;                         // own row's previous state
    float dcur = 0.f;
    if (pub) dcur = g_drive[myrow];           // drive at t=0

    const bool det = (tid < GBLK);            // detector threads: 1 per producer

    #pragma unroll 1
    for (int t = 0; t < T_STEPS; t++) {
        // prefetch next drive first: DRAM latency hides under the wait
        float dnext = dcur;
        if (pub && t + 1 < T_STEPS) dnext = g_drive[(size_t)(t + 1) * NRES + myrow];

        // ---- detect + stage s(t): 1 thread per producer line --------------
        if (det) {
            const unsigned long long* lp = &g_ex[t & 1][tid * 16];
            const unsigned tag = (unsigned)t;
            for (;;) {
                unsigned long long q[16];
                bool ready = true;
                #pragma unroll
                for (int k = 0; k < 8; k++) {
                    unsigned long long a, b;
                    asm volatile("ld.volatile.global.v2.u64 {%0,%1}, [%2];"
                                 : "=l"(a), "=l"(b) : "l"(lp + 2 * k));
                    q[2*k] = a; q[2*k+1] = b;
                    ready &= ((unsigned)(a >> 32) == tag) & ((unsigned)(b >> 32) == tag);
                }
                if (ready) {
                    float4* dst = reinterpret_cast<float4*>(&s_sh[t & 1][tid * 16]);
                    #pragma unroll
                    for (int k = 0; k < 4; k++)
                        dst[k] = make_float4(__uint_as_float((unsigned)q[4*k]),
                                             __uint_as_float((unsigned)q[4*k+1]),
                                             __uint_as_float((unsigned)q[4*k+2]),
                                             __uint_as_float((unsigned)q[4*k+3]));
                    break;
                }
            }
        }
        __syncthreads();                      // warps 4-7 parked here meanwhile

        // ---- packed f32x2 mat-vec partials --------------------------------
        const float4* s4 = reinterpret_cast<const float4*>(s_sh[t & 1]);
        unsigned long long acc0a = 0, acc0b = 0, acc1a = 0, acc1b = 0;
        #pragma unroll
        for (int j = 0; j < 16; j++) {
            float4 sv = s4[lane + 32 * j];
            asm("{\n\t"
                ".reg .b64 sA, sB;\n\t"
                "mov.b64 sA, {%4, %5};\n\t"
                "mov.b64 sB, {%6, %7};\n\t"
                "fma.rn.f32x2 %0, %8, sA, %0;\n\t"
                "fma.rn.f32x2 %1, %9, sB, %1;\n\t"
                "fma.rn.f32x2 %2, %10, sA, %2;\n\t"
                "fma.rn.f32x2 %3, %11, sB, %3;\n\t"
                "}"
                : "+l"(acc0a), "+l"(acc0b), "+l"(acc1a), "+l"(acc1b)
                : "f"(sv.x), "f"(sv.y), "f"(sv.z), "f"(sv.w),
                  "l"(w0[2*j]), "l"(w0[2*j+1]), "l"(w1[2*j]), "l"(w1[2*j+1]));
        }
        float e0, o0, e1, o1;
        asm("{\n\t.reg .b64 t0r;\n\tadd.rn.f32x2 t0r, %2, %3;\n\tmov.b64 {%0, %1}, t0r;\n\t}"
            : "=f"(e0), "=f"(o0) : "l"(acc0a), "l"(acc0b));
        asm("{\n\t.reg .b64 t1r;\n\tadd.rn.f32x2 t1r, %2, %3;\n\tmov.b64 {%0, %1}, t1r;\n\t}"
            : "=f"(e1), "=f"(o1) : "l"(acc1a), "l"(acc1b));
        float acc0 = e0 + o0;
        float acc1 = e1 + o1;
        #pragma unroll
        for (int off = 16; off > 0; off >>= 1) {
            acc0 += __shfl_xor_sync(0xffffffffu, acc0, off);
            acc1 += __shfl_xor_sync(0xffffffffu, acc1, off);
        }
        // butterfly => all lanes hold both sums; publisher lanes use their own

        // ---- update + publish (2 parallel chains per warp) ----------------
        if (pub) {
            float a  = (lane < 16) ? acc0 : acc1;
            float x  = dcur + a;
            float z  = __expf(2.f * x);                   // tanh = 1 - 2/(e^2x+1)
            float th = 1.f - __fdividef(2.f, z + 1.f);
            float ns = (1.f - LEAK) * sp + LEAK * th;
            sp = ns;
            unsigned long long p = ((unsigned long long)(unsigned)(t + 1) << 32)
                                 | __float_as_uint(ns);
            asm volatile("st.volatile.global.u64 [%0], %1;"
                         :: "l"(&g_ex[(t + 1) & 1][myrow]), "l"(p) : "memory");
            g_states[(size_t)t * NRES + myrow] = ns;
            dcur = dnext;
        }
        // no trailing barrier: next step stages into the other s_sh buffer,
        // and BAR(t+1) orders it against all readers of buffer t.
    }
}

// ---------------- kernel 3: out = states @ w_out^T + b_out ------------------
__global__ void proj_kernel(const float* __restrict__ w_out,
                            const float* __restrict__ b_out,
                            float* __restrict__ out) {
    __shared__ float s_sh[32][33];
    __shared__ float w_sh[DOUT][33];
    const int t0  = blockIdx.x * 32;
    const int tid = threadIdx.x;
    const int tx  = tid & 15;
    const int ty  = tid >> 4;
    float acc[2][4] = {};

    for (int kc = 0; kc < NRES; kc += 32) {
        for (int i = tid; i < 32 * 32; i += 256) {
            int r = i >> 5, k = i & 31;
            s_sh[r][k] = g_states[(size_t)(t0 + r) * NRES + kc + k];
        }
        for (int i = tid; i < DOUT * 32; i += 256) {
            int o = i >> 5, k = i & 31;
            w_sh[o][k] = w_out[(size_t)o * NRES + kc + k];
        }
        __syncthreads();
        for (int k = 0; k < 32; k++) {
            float sv[2], wv[4];
            #pragma unroll
            for (int i = 0; i < 2; i++) sv[i] = s_sh[ty * 2 + i][k];
            #pragma unroll
            for (int j = 0; j < 4; j++) wv[j] = w_sh[tx * 4 + j][k];
            #pragma unroll
            for (int i = 0; i < 2; i++)
                #pragma unroll
                for (int j = 0; j < 4; j++)
                    acc[i][j] += sv[i] * wv[j];
        }
        __syncthreads();
    }
    #pragma unroll
    for (int i = 0; i < 2; i++)
        #pragma unroll
        for (int j = 0; j < 4; j++)
            out[(size_t)(t0 + ty * 2 + i) * DOUT + tx * 4 + j] = acc[i][j] + b_out[tx * 4 + j];
}

// ---------------- launch ----------------------------------------------------
extern "C" void kernel_launch(void* const* d_in, const int* in_sizes, int n_in,
                              void* d_out, int out_size) {
    const float* u     = (const float*)d_in[0];  // (8192, 64)
    const float* noise = (const float*)d_in[1];  // (8192, 2048)
    const float* W_in  = (const float*)d_in[2];  // (2048, 64)
    const float* W     = (const float*)d_in[3];  // (2048, 2048)
    const float* w_out = (const float*)d_in[4];  // (64, 2048)
    const float* b_out = (const float*)d_in[5];  // (64,)
    float* out = (float*)d_out;                  // (8192, 64)

    init_kernel<<<NRES / 256, 256>>>();
    drive_kernel<<<dim3(NRES / 256, T_STEPS / TILE_T), 256>>>(u, noise, W_in);
    reservoir_kernel<<<GBLK, TPB>>>(W);
    proj_kernel<<<T_STEPS / 32, 256>>>(w_out, b_out, out);
}

// round 7
// speedup vs baseline: 2.1918x; 2.1918x over previous
#include <cuda_runtime.h>
#include <cstddef>

#define T_STEPS 8192
#define NRES    2048
#define DIN     64
#define DOUT    64
#define GBLK    128          // CTAs; 16 rows each (RF-forced: W lives in registers)
#define TPB     256
#define LEAK    0.3f
#define NOISE_L 0.01f
#define TILE_T  128

// ---------------- scratch (device globals: allocation-free) ----------------
__device__ float    g_drive [T_STEPS * NRES];   // 64 MB
__device__ float    g_states[T_STEPS * NRES];   // 64 MB
__device__ float    g_sbuf  [2][NRES];          // double-buffered reservoir state
__device__ unsigned g_ctr;                      // monotonic barrier counter

// ---------------- kernel 0: reset barrier + state (determinism) -------------
__global__ void init_kernel() {
    int i = blockIdx.x * blockDim.x + threadIdx.x;
    if (i < NRES) { g_sbuf[0][i] = 0.f; g_sbuf[1][i] = 0.f; }
    if (i == 0) g_ctr = 0u;
}

// ---------------- kernel 1: drive = u @ W_in^T + 0.01*noise -----------------
__global__ void drive_kernel(const float* __restrict__ u,
                             const float* __restrict__ noise,
                             const float* __restrict__ W_in) {
    __shared__ float4 u_sh[TILE_T * (DIN / 4)];
    const int n  = blockIdx.x * 256 + threadIdx.x;
    const int t0 = blockIdx.y * TILE_T;

    float4 w[DIN / 4];
    const float4* Wv = reinterpret_cast<const float4*>(W_in);
    #pragma unroll
    for (int j = 0; j < DIN / 4; j++) w[j] = Wv[(size_t)n * (DIN / 4) + j];

    const float4* uv = reinterpret_cast<const float4*>(u + (size_t)t0 * DIN);
    for (int i = threadIdx.x; i < TILE_T * (DIN / 4); i += 256) u_sh[i] = uv[i];
    __syncthreads();

    for (int t = 0; t < TILE_T; t++) {
        float acc = 0.f;
        #pragma unroll
        for (int j = 0; j < DIN / 4; j++) {
            float4 uu = u_sh[t * (DIN / 4) + j];
            acc += w[j].x * uu.x + w[j].y * uu.y + w[j].z * uu.z + w[j].w * uu.w;
        }
        size_t idx = (size_t)(t0 + t) * NRES + n;
        g_drive[idx] = acc + NOISE_L * noise[idx];
    }
}

// ---------------- kernel 2: persistent reservoir ----------------------------
// R1 skeleton: counter barrier + single coalesced __ldcg staging sweep.
// Improvements: monotonic release/acquire barrier (no fences, no gen word),
// f32x2 FMAs, fast tanh, dual publisher lanes, prefetch-before-wait.
__global__ void __launch_bounds__(TPB, 1) reservoir_kernel(const float* __restrict__ W) {
    __shared__ float s_sh[NRES];              // 8 KB staged state

    const int tid  = threadIdx.x;
    const int cta  = blockIdx.x;
    const int warp = tid >> 5;
    const int lane = tid & 31;
    const int r0   = cta * 16 + warp * 2;

    // One-time: load W slice, pack column pairs into 64-bit (f32x2) registers
    const float4* Wv = reinterpret_cast<const float4*>(W);
    unsigned long long w0[32], w1[32];
    #pragma unroll
    for (int j = 0; j < 16; j++) {
        float4 a = Wv[(size_t)r0 * (NRES / 4) + lane + 32 * j];
        float4 b = Wv[(size_t)(r0 + 1) * (NRES / 4) + lane + 32 * j];
        w0[2*j]   = ((unsigned long long)__float_as_uint(a.y) << 32) | __float_as_uint(a.x);
        w0[2*j+1] = ((unsigned long long)__float_as_uint(a.w) << 32) | __float_as_uint(a.z);
        w1[2*j]   = ((unsigned long long)__float_as_uint(b.y) << 32) | __float_as_uint(b.x);
        w1[2*j+1] = ((unsigned long long)__float_as_uint(b.w) << 32) | __float_as_uint(b.z);
    }

    const bool pub   = (lane & 15) == 0;      // lanes 0 and 16 publish
    const int  myrow = r0 + (lane >> 4);      // lane0 -> r0, lane16 -> r0+1
    float sp   = 0.f;                         // own row's previous state
    float dcur = 0.f;
    if (pub) dcur = g_drive[myrow];           // drive at t=0

    #pragma unroll 1
    for (int t = 0; t < T_STEPS; t++) {
        // ---- stage s(t): ONE coalesced L1-bypassing sweep, no retries ------
        const float4* sin = reinterpret_cast<const float4*>(g_sbuf[t & 1]);
        float4 v0 = __ldcg(&sin[tid]);
        float4 v1 = __ldcg(&sin[tid + 256]);
        reinterpret_cast<float4*>(s_sh)[tid]       = v0;
        reinterpret_cast<float4*>(s_sh)[tid + 256] = v1;
        __syncthreads();

        // ---- packed f32x2 mat-vec partials --------------------------------
        const float4* s4 = reinterpret_cast<const float4*>(s_sh);
        unsigned long long acc0a = 0, acc0b = 0, acc1a = 0, acc1b = 0;
        #pragma unroll
        for (int j = 0; j < 16; j++) {
            float4 sv = s4[lane + 32 * j];
            asm("{\n\t"
                ".reg .b64 sA, sB;\n\t"
                "mov.b64 sA, {%4, %5};\n\t"
                "mov.b64 sB, {%6, %7};\n\t"
                "fma.rn.f32x2 %0, %8, sA, %0;\n\t"
                "fma.rn.f32x2 %1, %9, sB, %1;\n\t"
                "fma.rn.f32x2 %2, %10, sA, %2;\n\t"
                "fma.rn.f32x2 %3, %11, sB, %3;\n\t"
                "}"
                : "+l"(acc0a), "+l"(acc0b), "+l"(acc1a), "+l"(acc1b)
                : "f"(sv.x), "f"(sv.y), "f"(sv.z), "f"(sv.w),
                  "l"(w0[2*j]), "l"(w0[2*j+1]), "l"(w1[2*j]), "l"(w1[2*j+1]));
        }
        float e0, o0, e1, o1;
        asm("{\n\t.reg .b64 t0r;\n\tadd.rn.f32x2 t0r, %2, %3;\n\tmov.b64 {%0, %1}, t0r;\n\t}"
            : "=f"(e0), "=f"(o0) : "l"(acc0a), "l"(acc0b));
        asm("{\n\t.reg .b64 t1r;\n\tadd.rn.f32x2 t1r, %2, %3;\n\tmov.b64 {%0, %1}, t1r;\n\t}"
            : "=f"(e1), "=f"(o1) : "l"(acc1a), "l"(acc1b));
        float acc0 = e0 + o0;
        float acc1 = e1 + o1;
        #pragma unroll
        for (int off = 16; off > 0; off >>= 1) {
            acc0 += __shfl_xor_sync(0xffffffffu, acc0, off);
            acc1 += __shfl_xor_sync(0xffffffffu, acc1, off);
        }
        // butterfly => all lanes hold both sums

        // ---- update + publish (2 parallel chains per warp) ----------------
        float dnext = dcur;
        if (pub) {
            float a  = (lane < 16) ? acc0 : acc1;
            float x  = dcur + a;
            float z  = __expf(2.f * x);                   // tanh = 1 - 2/(e^2x+1)
            float th = 1.f - __fdividef(2.f, z + 1.f);
            float ns = (1.f - LEAK) * sp + LEAK * th;
            sp = ns;
            g_sbuf[(t + 1) & 1][myrow] = ns;              // plain store; release below
            g_states[(size_t)t * NRES + myrow] = ns;
            // prefetch next drive BEFORE the wait: latency hides under the spin
            if (t + 1 < T_STEPS) dnext = g_drive[(size_t)(t + 1) * NRES + myrow];
        }

        // ---- monotonic grid barrier (release-red / acquire-ld) ------------
        __syncthreads();                      // all CTA stores precede arrival
        if (tid == 0) {
            asm volatile("red.release.gpu.global.add.u32 [%0], 1;"
                         :: "l"(&g_ctr) : "memory");
            const unsigned target = (unsigned)(t + 1) * GBLK;
            unsigned c;
            do {
                asm volatile("ld.acquire.gpu.global.u32 %0, [%1];"
                             : "=r"(c) : "l"(&g_ctr));
            } while (c < target);
        }
        __syncthreads();                      // rest of CTA parked here
        dcur = dnext;
    }
}

// ---------------- kernel 3: out = states @ w_out^T + b_out ------------------
__global__ void proj_kernel(const float* __restrict__ w_out,
                            const float* __restrict__ b_out,
                            float* __restrict__ out) {
    __shared__ float s_sh[32][33];
    __shared__ float w_sh[DOUT][33];
    const int t0  = blockIdx.x * 32;
    const int tid = threadIdx.x;
    const int tx  = tid & 15;
    const int ty  = tid >> 4;
    float acc[2][4] = {};

    for (int kc = 0; kc < NRES; kc += 32) {
        for (int i = tid; i < 32 * 32; i += 256) {
            int r = i >> 5, k = i & 31;
            s_sh[r][k] = g_states[(size_t)(t0 + r) * NRES + kc + k];
        }
        for (int i = tid; i < DOUT * 32; i += 256) {
            int o = i >> 5, k = i & 31;
            w_sh[o][k] = w_out[(size_t)o * NRES + kc + k];
        }
        __syncthreads();
        for (int k = 0; k < 32; k++) {
            float sv[2], wv[4];
            #pragma unroll
            for (int i = 0; i < 2; i++) sv[i] = s_sh[ty * 2 + i][k];
            #pragma unroll
            for (int j = 0; j < 4; j++) wv[j] = w_sh[tx * 4 + j][k];
            #pragma unroll
            for (int i = 0; i < 2; i++)
                #pragma unroll
                for (int j = 0; j < 4; j++)
                    acc[i][j] += sv[i] * wv[j];
        }
        __syncthreads();
    }
    #pragma unroll
    for (int i = 0; i < 2; i++)
        #pragma unroll
        for (int j = 0; j < 4; j++)
            out[(size_t)(t0 + ty * 2 + i) * DOUT + tx * 4 + j] = acc[i][j] + b_out[tx * 4 + j];
}

// ---------------- launch ----------------------------------------------------
extern "C" void kernel_launch(void* const* d_in, const int* in_sizes, int n_in,
                              void* d_out, int out_size) {
    const float* u     = (const float*)d_in[0];  // (8192, 64)
    const float* noise = (const float*)d_in[1];  // (8192, 2048)
    const float* W_in  = (const float*)d_in[2];  // (2048, 64)
    const float* W     = (const float*)d_in[3];  // (2048, 2048)
    const float* w_out = (const float*)d_in[4];  // (64, 2048)
    const float* b_out = (const float*)d_in[5];  // (64,)
    float* out = (float*)d_out;                  // (8192, 64)

    init_kernel<<<NRES / 256, 256>>>();
    drive_kernel<<<dim3(NRES / 256, T_STEPS / TILE_T), 256>>>(u, noise, W_in);
    reservoir_kernel<<<GBLK, TPB>>>(W);
    proj_kernel<<<T_STEPS / 32, 256>>>(w_out, b_out, out);
}